// round 16
// baseline (speedup 1.0000x reference)
#include <cuda_runtime.h>
#include <cuda_bf16.h>

#define BB 16
#define NN 256
#define HIDD 512
#define HH 8
#define MLPH 64
#define BN (BB*NN)   // 4096

__device__ __align__(256) float g_vh[BN*HIDD];
__device__ __align__(256) float g_scores[BB*HH*NN*NN];   // holds 0.1*pair bias
__device__ __align__(256) float g_hiS[BN*MLPH];
__device__ __align__(256) float g_hiO[BN*MLPH];
__device__ __align__(256) __nv_bfloat16 g_Ahi[BN*HIDD];
__device__ __align__(256) __nv_bfloat16 g_Alo[BN*HIDD];
__device__ __align__(256) __nv_bfloat16 g_WhiT[HIDD*HIDD];
__device__ __align__(256) __nv_bfloat16 g_WloT[HIDD*HIDD];
__device__ __align__(256) __nv_bfloat16 g_qhh[BN*HIDD];
__device__ __align__(256) __nv_bfloat16 g_qhl[BN*HIDD];
__device__ __align__(256) __nv_bfloat16 g_khh[BN*HIDD];
__device__ __align__(256) __nv_bfloat16 g_khl[BN*HIDD];

// ============================ small asm helpers =============================
__device__ __forceinline__ unsigned smem_u32(const void* p) {
    unsigned a;
    asm("{ .reg .u64 t; cvta.to.shared.u64 t, %1; cvt.u32.u64 %0, t; }"
        : "=r"(a) : "l"(p));
    return a;
}
__device__ __forceinline__ void cp16(unsigned dst, const void* src) {
    asm volatile("cp.async.cg.shared.global [%0], [%1], 16;"
                 :: "r"(dst), "l"(src) : "memory");
}
__device__ __forceinline__ void cp_commit() {
    asm volatile("cp.async.commit_group;" ::: "memory");
}
__device__ __forceinline__ void mma_bf16(float* d, const unsigned* a, const unsigned* b) {
    asm volatile("mma.sync.aligned.m16n8k16.row.col.f32.bf16.bf16.f32 "
                 "{%0,%1,%2,%3}, {%4,%5,%6,%7}, {%8,%9}, {%0,%1,%2,%3};"
                 : "+f"(d[0]), "+f"(d[1]), "+f"(d[2]), "+f"(d[3])
                 : "r"(a[0]), "r"(a[1]), "r"(a[2]), "r"(a[3]),
                   "r"(b[0]), "r"(b[1]));
}
__device__ __forceinline__ unsigned pk(float a, float b) {
    __nv_bfloat162 v = __floats2bfloat162_rn(a, b);
    return *(unsigned*)&v;
}
__device__ __forceinline__ float resid(float x) {
    return x - __bfloat162float(__float2bfloat16_rn(x));
}
__device__ __forceinline__ unsigned pklo(float a, float b) {
    return pk(resid(a), resid(b));
}

// =================== prep: fp32 -> bf16 hi/lo ===============================
__global__ void prep_a_kernel(const float* __restrict__ A,
                              __nv_bfloat16* __restrict__ hi,
                              __nv_bfloat16* __restrict__ lo, int n4)
{
    int i = blockIdx.x * blockDim.x + threadIdx.x;
    if (i >= n4) return;
    float4 a = ((const float4*)A)[i];
    __nv_bfloat16 h0 = __float2bfloat16(a.x), h1 = __float2bfloat16(a.y);
    __nv_bfloat16 h2 = __float2bfloat16(a.z), h3 = __float2bfloat16(a.w);
    __nv_bfloat16 l0 = __float2bfloat16(a.x - __bfloat162float(h0));
    __nv_bfloat16 l1 = __float2bfloat16(a.y - __bfloat162float(h1));
    __nv_bfloat16 l2 = __float2bfloat16(a.z - __bfloat162float(h2));
    __nv_bfloat16 l3 = __float2bfloat16(a.w - __bfloat162float(h3));
    ((__nv_bfloat162*)hi)[i*2]   = __nv_bfloat162(h0, h1);
    ((__nv_bfloat162*)hi)[i*2+1] = __nv_bfloat162(h2, h3);
    ((__nv_bfloat162*)lo)[i*2]   = __nv_bfloat162(l0, l1);
    ((__nv_bfloat162*)lo)[i*2+1] = __nv_bfloat162(l2, l3);
}

// W[k][n] -> WT[n][k] bf16 hi/lo (tiled transpose)
__global__ __launch_bounds__(256) void prep_w_kernel(
    const float* __restrict__ W,
    __nv_bfloat16* __restrict__ hiT, __nv_bfloat16* __restrict__ loT)
{
    __shared__ float tile[32][33];
    int n0 = blockIdx.x*32, k0 = blockIdx.y*32;
    int tx = threadIdx.x & 31, ty = threadIdx.x >> 5;
    for (int r = ty; r < 32; r += 8)
        tile[r][tx] = W[(k0 + r)*512 + n0 + tx];
    __syncthreads();
    for (int rn = ty; rn < 32; rn += 8) {
        float w = tile[tx][rn];
        __nv_bfloat16 h = __float2bfloat16(w);
        __nv_bfloat16 l = __float2bfloat16(w - __bfloat162float(h));
        hiT[(n0 + rn)*512 + k0 + tx] = h;
        loT[(n0 + rn)*512 + k0 + tx] = l;
    }
}

// =================== HMMA GEMM: out = scale*(A@W + bias) ====================
// If C != nullptr: write fp32 C. Else: write bf16 hi/lo to Chi/Clo.
#define LDAB 80
#define ARR_B (128*LDAB)
#define STAGE_B (4*ARR_B)
#define SMEM_HM (2*STAGE_B)

__global__ __launch_bounds__(256, 1) void gemm_hmma_kernel(
    const __nv_bfloat16* __restrict__ Ahi, const __nv_bfloat16* __restrict__ Alo,
    const __nv_bfloat16* __restrict__ Bhi, const __nv_bfloat16* __restrict__ Blo,
    const float* __restrict__ bias, float* __restrict__ C,
    __nv_bfloat16* __restrict__ Chi, __nv_bfloat16* __restrict__ Clo, float scale)
{
    extern __shared__ char smc[];
    unsigned sb = smem_u32(smc);
    int t = threadIdx.x, lane = t & 31, wid = t >> 5;
    int m0 = blockIdx.y*128, n0 = blockIdx.x*128;
    int wm = (wid >> 2)*64, wn = (wid & 3)*32;
    int g = lane >> 2, tig = lane & 3;

    float acc[4][4][4] = {};

    auto stage_load = [&](int kc, int s) {
        unsigned base = sb + s*STAGE_B;
        #pragma unroll
        for (int i = 0; i < 2; i++) {
            int idx = t + i*256;
            int r = idx >> 2;
            int cb = (idx & 3)*16;
            unsigned d = base + r*LDAB + cb;
            int goff = kc + cb/2;
            cp16(d,            &Ahi[(m0 + r)*512 + goff]);
            cp16(d + ARR_B,    &Alo[(m0 + r)*512 + goff]);
            cp16(d + 2*ARR_B,  &Bhi[(n0 + r)*512 + goff]);
            cp16(d + 3*ARR_B,  &Blo[(n0 + r)*512 + goff]);
        }
        cp_commit();
    };

    stage_load(0, 0);
    stage_load(32, 1);

    #pragma unroll 1
    for (int kc = 0; kc < 16; kc++) {
        int s = kc & 1;
        if (kc == 15) asm volatile("cp.async.wait_group 0;" ::: "memory");
        else          asm volatile("cp.async.wait_group 1;" ::: "memory");
        __syncthreads();

        const char* stg = smc + s*STAGE_B;

        #pragma unroll
        for (int ks = 0; ks < 32; ks += 16) {
            unsigned ah[4][4], al[4][4], bh[4][2], bl[4][2];
            #pragma unroll
            for (int mi = 0; mi < 4; mi++) {
                int r0 = wm + mi*16 + g;
                int c0 = (ks + 2*tig)*2;
                ah[mi][0] = *(const unsigned*)(stg + r0*LDAB + c0);
                ah[mi][1] = *(const unsigned*)(stg + (r0+8)*LDAB + c0);
                ah[mi][2] = *(const unsigned*)(stg + r0*LDAB + c0 + 16);
                ah[mi][3] = *(const unsigned*)(stg + (r0+8)*LDAB + c0 + 16);
                al[mi][0] = *(const unsigned*)(stg + ARR_B + r0*LDAB + c0);
                al[mi][1] = *(const unsigned*)(stg + ARR_B + (r0+8)*LDAB + c0);
                al[mi][2] = *(const unsigned*)(stg + ARR_B + r0*LDAB + c0 + 16);
                al[mi][3] = *(const unsigned*)(stg + ARR_B + (r0+8)*LDAB + c0 + 16);
            }
            #pragma unroll
            for (int ni = 0; ni < 4; ni++) {
                int nr = wn + ni*8 + g;
                int c0 = (ks + 2*tig)*2;
                bh[ni][0] = *(const unsigned*)(stg + 2*ARR_B + nr*LDAB + c0);
                bh[ni][1] = *(const unsigned*)(stg + 2*ARR_B + nr*LDAB + c0 + 16);
                bl[ni][0] = *(const unsigned*)(stg + 3*ARR_B + nr*LDAB + c0);
                bl[ni][1] = *(const unsigned*)(stg + 3*ARR_B + nr*LDAB + c0 + 16);
            }
            #pragma unroll
            for (int mi = 0; mi < 4; mi++)
                #pragma unroll
                for (int ni = 0; ni < 4; ni++) {
                    mma_bf16(acc[mi][ni], ah[mi], bh[ni]);
                    mma_bf16(acc[mi][ni], ah[mi], bl[ni]);
                    mma_bf16(acc[mi][ni], al[mi], bh[ni]);
                }
        }
        __syncthreads();
        if (kc + 2 < 16) stage_load((kc + 2)*32, s);
    }

    #pragma unroll
    for (int mi = 0; mi < 4; mi++) {
        int row = m0 + wm + mi*16 + g;
        #pragma unroll
        for (int ni = 0; ni < 4; ni++) {
            int col = n0 + wn + ni*8 + 2*tig;
            float b0 = bias[col], b1 = bias[col + 1];
            float o00 = scale*(acc[mi][ni][0] + b0);
            float o01 = scale*(acc[mi][ni][1] + b1);
            float o10 = scale*(acc[mi][ni][2] + b0);
            float o11 = scale*(acc[mi][ni][3] + b1);
            if (C) {
                *(float2*)&C[row*512 + col]       = make_float2(o00, o01);
                *(float2*)&C[(row + 8)*512 + col] = make_float2(o10, o11);
            } else {
                *(unsigned*)&Chi[row*512 + col]       = pk(o00, o01);
                *(unsigned*)&Clo[row*512 + col]       = pklo(o00, o01);
                *(unsigned*)&Chi[(row + 8)*512 + col] = pk(o10, o11);
                *(unsigned*)&Clo[(row + 8)*512 + col] = pklo(o10, o11);
            }
        }
    }
}

// ============================ hfeat: hi = feat@Wa + b1 ======================
__global__ void hfeat_kernel(
    const float* __restrict__ fs, const float* __restrict__ fo,
    const float* __restrict__ fsW1, const float* __restrict__ fsb1,
    const float* __restrict__ foW1, const float* __restrict__ fob1)
{
    int idx = blockIdx.x * blockDim.x + threadIdx.x;
    if (idx >= BN*MLPH) return;
    int bn = idx >> 6, m = idx & 63;
    float s_i = fsb1[m], o_i = fob1[m];
    #pragma unroll
    for (int f = 0; f < 8; f++) {
        float vs = fs[bn*8 + f], vo = fo[bn*8 + f];
        s_i += vs * fsW1[f*64 + m];
        o_i += vo * foW1[f*64 + m];
    }
    g_hiS[idx] = s_i; g_hiO[idx] = o_i;
}

// =================== pair bias via back-to-back HMMA (STORE mode) ===========
// Writes 0.1*pair into g_scores (no read-modify-write).
#define PAIR_SMEMF 12288
#define FB1(ml,nt,r,hl) fb1[((((ml)*8+(nt))*2+(r))*2+(hl))*32 + lane]
#define FB2(ml,ks,r,hl) fb2[((((ml)*4+(ks))*2+(r))*2+(hl))*32 + lane]

__global__ __launch_bounds__(256) void pair_mma_kernel(
    const float* __restrict__ fs, const float* __restrict__ fo,
    const float* __restrict__ fsW1, const float* __restrict__ fsW2, const float* __restrict__ fsb2,
    const float* __restrict__ foW1, const float* __restrict__ foW2, const float* __restrict__ fob2)
{
    extern __shared__ float ps[];
    float* sW1 = ps;
    float* sW2 = ps + 2048;
    float* sF  = ps + 3072;
    float* sHi = ps + 7168;
    unsigned* fb1 = (unsigned*)(ps + 9216);
    unsigned* fb2 = (unsigned*)(ps + 11264);

    int t = threadIdx.x, lane = t & 31, w = t >> 5;
    int g = lane >> 2;
    int tig = lane & 3;
    int ig = blockIdx.x, b = blockIdx.y;
    int i0 = ig*16;

    for (int idx = t; idx < 1024; idx += 256) {
        int r = idx >> 6, c = idx & 63;
        sW1[idx]        = fsW1[(8+r)*64 + c];
        sW1[1024+idx]   = foW1[(8+r)*64 + c];
        sHi[idx]        = g_hiS[(b*NN + i0 + r)*64 + c];
        sHi[1024+idx]   = g_hiO[(b*NN + i0 + r)*64 + c];
    }
    for (int idx = t; idx < 512; idx += 256) {
        sW2[idx]       = fsW2[idx];
        sW2[512+idx]   = foW2[idx];
    }
    for (int idx = t; idx < 2048; idx += 256) {
        sF[idx]        = fs[b*NN*8 + idx];
        sF[2048+idx]   = fo[b*NN*8 + idx];
    }
    __syncthreads();

    if (w == 0) {
        #pragma unroll
        for (int ml = 0; ml < 2; ml++)
            #pragma unroll
            for (int nt = 0; nt < 8; nt++) {
                int n = nt*8 + g;
                const float* W = sW1 + ml*1024;
                float w00 = W[(2*tig+8)*64 + n], w01 = W[(2*tig+9)*64 + n];
                float w10 = W[(2*tig)*64 + n],   w11 = W[(2*tig+1)*64 + n];
                FB1(ml,nt,0,0) = pk(w00, w01);
                FB1(ml,nt,0,1) = pklo(w00, w01);
                FB1(ml,nt,1,0) = pk(w10, w11);
                FB1(ml,nt,1,1) = pklo(w10, w11);
            }
    } else if (w == 1) {
        #pragma unroll
        for (int ml = 0; ml < 2; ml++)
            #pragma unroll
            for (int ks = 0; ks < 4; ks++) {
                const float* W = sW2 + ml*512;
                float w00 = W[(16*ks+2*tig)*8 + g],   w01 = W[(16*ks+2*tig+1)*8 + g];
                float w10 = W[(16*ks+2*tig+8)*8 + g], w11 = W[(16*ks+2*tig+9)*8 + g];
                FB2(ml,ks,0,0) = pk(w00, w01);
                FB2(ml,ks,0,1) = pklo(w00, w01);
                FB2(ml,ks,1,0) = pk(w10, w11);
                FB2(ml,ks,1,1) = pklo(w10, w11);
            }
    }
    __syncthreads();

    float b2r[2][2];
    b2r[0][0] = fsb2[2*tig]; b2r[0][1] = fsb2[2*tig+1];
    b2r[1][0] = fob2[2*tig]; b2r[1][1] = fob2[2*tig+1];

    float accL1[8][4];
    unsigned upk[8][2];

    #pragma unroll 1
    for (int jh = 0; jh < 2; jh++) {
        int jbase = jh*128 + w*16;
        float fjv[2][2][2];
        unsigned fa2h[2], fa3h[2], fa2l[2], fa3l[2];
        #pragma unroll
        for (int ml = 0; ml < 2; ml++) {
            const float* F = sF + ml*2048;
            float f00 = F[(jbase+g)*8 + 2*tig],   f01 = F[(jbase+g)*8 + 2*tig+1];
            float f10 = F[(jbase+g+8)*8 + 2*tig], f11 = F[(jbase+g+8)*8 + 2*tig+1];
            fjv[ml][0][0] = f00; fjv[ml][0][1] = f01;
            fjv[ml][1][0] = f10; fjv[ml][1][1] = f11;
            fa2h[ml] = pk(f00, f01); fa2l[ml] = pklo(f00, f01);
            fa3h[ml] = pk(f10, f11); fa3l[ml] = pklo(f10, f11);
        }

        #pragma unroll 1
        for (int ii = 0; ii < 16; ii++) {
            float pacc[4] = {0.f, 0.f, 0.f, 0.f};
            #pragma unroll
            for (int ml = 0; ml < 2; ml++) {
                const float* F = sF + ml*2048;
                float fi0 = F[(i0+ii)*8 + 2*tig], fi1 = F[(i0+ii)*8 + 2*tig+1];
                float d00 = fabsf(fi0 - fjv[ml][0][0]), d01 = fabsf(fi1 - fjv[ml][0][1]);
                float d10 = fabsf(fi0 - fjv[ml][1][0]), d11 = fabsf(fi1 - fjv[ml][1][1]);
                unsigned ah[4], al[4];
                ah[0] = pk(d00, d01);  ah[1] = pk(d10, d11);
                ah[2] = fa2h[ml];      ah[3] = fa3h[ml];
                al[0] = pklo(d00, d01); al[1] = pklo(d10, d11);
                al[2] = fa2l[ml];      al[3] = fa3l[ml];

                const float* Hi = sHi + ml*1024 + ii*64;
                #pragma unroll
                for (int nt = 0; nt < 8; nt++) {
                    float h0 = Hi[8*nt + 2*tig], h1 = Hi[8*nt + 2*tig + 1];
                    accL1[nt][0] = h0; accL1[nt][1] = h1;
                    accL1[nt][2] = h0; accL1[nt][3] = h1;
                    unsigned bh[2] = {FB1(ml,nt,0,0), FB1(ml,nt,1,0)};
                    unsigned bl[2] = {FB1(ml,nt,0,1), FB1(ml,nt,1,1)};
                    mma_bf16(accL1[nt], ah, bh);
                    mma_bf16(accL1[nt], al, bh);
                    mma_bf16(accL1[nt], ah, bl);
                }
                #pragma unroll
                for (int nt = 0; nt < 8; nt++) {
                    upk[nt][0] = pk(fmaxf(accL1[nt][0], 0.f), fmaxf(accL1[nt][1], 0.f));
                    upk[nt][1] = pk(fmaxf(accL1[nt][2], 0.f), fmaxf(accL1[nt][3], 0.f));
                }
                float acc2[4];
                acc2[0] = b2r[ml][0]; acc2[1] = b2r[ml][1];
                acc2[2] = b2r[ml][0]; acc2[3] = b2r[ml][1];
                #pragma unroll
                for (int ks = 0; ks < 4; ks++) {
                    unsigned a2[4] = {upk[2*ks][0], upk[2*ks][1],
                                      upk[2*ks+1][0], upk[2*ks+1][1]};
                    unsigned bh2[2] = {FB2(ml,ks,0,0), FB2(ml,ks,1,0)};
                    unsigned bl2[2] = {FB2(ml,ks,0,1), FB2(ml,ks,1,1)};
                    mma_bf16(acc2, a2, bh2);
                    mma_bf16(acc2, a2, bl2);
                }
                pacc[0] += acc2[0]; pacc[1] += acc2[1];
                pacc[2] += acc2[2]; pacc[3] += acc2[3];
            }
            int i = i0 + ii;
            float* s0 = &g_scores[((b*HH + 2*tig)*NN + i)*NN + jbase];
            float* s1 = &g_scores[((b*HH + 2*tig + 1)*NN + i)*NN + jbase];
            s0[g]     = 0.1f * pacc[0];
            s1[g]     = 0.1f * pacc[1];
            s0[g + 8] = 0.1f * pacc[2];
            s1[g + 8] = 0.1f * pacc[3];
        }
    }
}

// =================== fused attention: QK + bias + softmax + PV ==============
// CTA = (i-tile of 32, b*h). 8 warps, 256 threads, smem-resident S row block.
#define FQ_LD 144                 // Q/K smem row: 64 bf16 + pad
#define FS_LDW 260                // S smem row in floats
#define FP_LD 528                 // P/VT smem row: 256 bf16 + pad
#define OFF_QHI 0
#define OFF_QLO 4608
#define OFF_KHI 9216
#define OFF_KLO 46080
#define OFF_PHI OFF_KHI           // P reuses K region after QK
#define OFF_PLO (OFF_KHI + 16896)
#define OFF_S   82944
#define OFF_VTHI 116224
#define OFF_VTLO 150016
#define SMEM_FUSED 183808

__global__ __launch_bounds__(256, 1) void attn_fused_kernel(const float* __restrict__ tbias)
{
    extern __shared__ char smf[];
    unsigned sb = smem_u32(smf);
    int t = threadIdx.x, lane = t & 31, w = t >> 5;
    int g = lane >> 2, tig = lane & 3;
    int i0 = blockIdx.x * 32;
    int bh = blockIdx.y; int b = bh >> 3, h = bh & 7;

    // stage Q (32x64) and K (256x64) hi/lo via cp.async
    {
        int r = t >> 3, cb = (t & 7) * 16;
        int src = (b*NN + i0 + r)*HIDD + h*64;
        cp16(sb + OFF_QHI + r*FQ_LD + cb, (const char*)&g_qhh[src] + cb);
        cp16(sb + OFF_QLO + r*FQ_LD + cb, (const char*)&g_qhl[src] + cb);
    }
    #pragma unroll
    for (int it = 0; it < 8; it++) {
        int idx = t + it*256;
        int r = idx >> 3, cb = (idx & 7) * 16;
        int src = (b*NN + r)*HIDD + h*64;
        cp16(sb + OFF_KHI + r*FQ_LD + cb, (const char*)&g_khh[src] + cb);
        cp16(sb + OFF_KLO + r*FQ_LD + cb, (const char*)&g_khl[src] + cb);
    }
    cp_commit();

    // V transpose + hi/lo split into VT[d][j] (independent smem region)
    #pragma unroll 1
    for (int e = t; e < 256*64; e += 256) {
        int j = e >> 6, d = e & 63;
        float vv = g_vh[(b*NN + j)*HIDD + h*64 + d];
        __nv_bfloat16 hi = __float2bfloat16_rn(vv);
        *(__nv_bfloat16*)(smf + OFF_VTHI + d*FP_LD + j*2) = hi;
        *(__nv_bfloat16*)(smf + OFF_VTLO + d*FP_LD + j*2) =
            __float2bfloat16_rn(vv - __bfloat162float(hi));
    }

    asm volatile("cp.async.wait_group 0;" ::: "memory");
    __syncthreads();

    // ---- QK: warp w covers j in [w*32, w*32+32) ----
    {
        float acc[2][4][4] = {};
        #pragma unroll
        for (int ks = 0; ks < 4; ks++) {
            int c0 = ks*32 + 4*tig;
            unsigned ah[2][4], al[2][4], kb[4][2], kl[4][2];
            #pragma unroll
            for (int mi = 0; mi < 2; mi++) {
                int r0 = mi*16 + g;
                ah[mi][0] = *(const unsigned*)(smf + OFF_QHI + r0*FQ_LD + c0);
                ah[mi][1] = *(const unsigned*)(smf + OFF_QHI + (r0+8)*FQ_LD + c0);
                ah[mi][2] = *(const unsigned*)(smf + OFF_QHI + r0*FQ_LD + c0 + 16);
                ah[mi][3] = *(const unsigned*)(smf + OFF_QHI + (r0+8)*FQ_LD + c0 + 16);
                al[mi][0] = *(const unsigned*)(smf + OFF_QLO + r0*FQ_LD + c0);
                al[mi][1] = *(const unsigned*)(smf + OFF_QLO + (r0+8)*FQ_LD + c0);
                al[mi][2] = *(const unsigned*)(smf + OFF_QLO + r0*FQ_LD + c0 + 16);
                al[mi][3] = *(const unsigned*)(smf + OFF_QLO + (r0+8)*FQ_LD + c0 + 16);
            }
            #pragma unroll
            for (int ni = 0; ni < 4; ni++) {
                int nr = w*32 + ni*8 + g;
                kb[ni][0] = *(const unsigned*)(smf + OFF_KHI + nr*FQ_LD + c0);
                kb[ni][1] = *(const unsigned*)(smf + OFF_KHI + nr*FQ_LD + c0 + 16);
                kl[ni][0] = *(const unsigned*)(smf + OFF_KLO + nr*FQ_LD + c0);
                kl[ni][1] = *(const unsigned*)(smf + OFF_KLO + nr*FQ_LD + c0 + 16);
            }
            #pragma unroll
            for (int mi = 0; mi < 2; mi++)
                #pragma unroll
                for (int ni = 0; ni < 4; ni++) {
                    mma_bf16(acc[mi][ni], ah[mi], kb[ni]);
                    mma_bf16(acc[mi][ni], al[mi], kb[ni]);
                    mma_bf16(acc[mi][ni], ah[mi], kl[ni]);
                }
        }
        float* S = (float*)(smf + OFF_S);
        #pragma unroll
        for (int mi = 0; mi < 2; mi++)
            #pragma unroll
            for (int ni = 0; ni < 4; ni++) {
                int row = mi*16 + g, col = w*32 + ni*8 + 2*tig;
                S[row*FS_LDW + col]       = acc[mi][ni][0];
                S[row*FS_LDW + col + 1]   = acc[mi][ni][1];
                S[(row+8)*FS_LDW + col]   = acc[mi][ni][2];
                S[(row+8)*FS_LDW + col+1] = acc[mi][ni][3];
            }
    }
    __syncthreads();

    // ---- add tree bias + pair bias (coalesced streams) ----
    {
        const float* tb = &tbias[((b*HH + h)*NN + i0)*NN];
        const float* pb = &g_scores[((b*HH + h)*NN + i0)*NN];
        float* S = (float*)(smf + OFF_S);
        #pragma unroll 1
        for (int e = t; e < 32*256; e += 256) {
            int r = e >> 8, c = e & 255;
            S[r*FS_LDW + c] += tb[r*256 + c] + pb[r*256 + c];
        }
    }
    __syncthreads();

    // ---- softmax: warp w handles rows 4w..4w+3; write P bf16 hi/lo ----
    #pragma unroll
    for (int rr = 0; rr < 4; rr++) {
        int row = w*4 + rr;
        float* srow = (float*)(smf + OFF_S) + row*FS_LDW;
        float4 v0 = *(float4*)&srow[lane*8];
        float4 v1 = *(float4*)&srow[lane*8 + 4];
        float mx = fmaxf(fmaxf(fmaxf(v0.x, v0.y), fmaxf(v0.z, v0.w)),
                         fmaxf(fmaxf(v1.x, v1.y), fmaxf(v1.z, v1.w)));
        #pragma unroll
        for (int o = 16; o > 0; o >>= 1)
            mx = fmaxf(mx, __shfl_xor_sync(0xffffffffu, mx, o));
        v0.x = __expf(v0.x - mx); v0.y = __expf(v0.y - mx);
        v0.z = __expf(v0.z - mx); v0.w = __expf(v0.w - mx);
        v1.x = __expf(v1.x - mx); v1.y = __expf(v1.y - mx);
        v1.z = __expf(v1.z - mx); v1.w = __expf(v1.w - mx);
        float sm = v0.x + v0.y + v0.z + v0.w + v1.x + v1.y + v1.z + v1.w;
        #pragma unroll
        for (int o = 16; o > 0; o >>= 1)
            sm += __shfl_xor_sync(0xffffffffu, sm, o);
        float inv = 1.f / sm;
        v0.x *= inv; v0.y *= inv; v0.z *= inv; v0.w *= inv;
        v1.x *= inv; v1.y *= inv; v1.z *= inv; v1.w *= inv;
        uint4 hi4, lo4;
        hi4.x = pk(v0.x, v0.y);   lo4.x = pklo(v0.x, v0.y);
        hi4.y = pk(v0.z, v0.w);   lo4.y = pklo(v0.z, v0.w);
        hi4.z = pk(v1.x, v1.y);   lo4.z = pklo(v1.x, v1.y);
        hi4.w = pk(v1.z, v1.w);   lo4.w = pklo(v1.z, v1.w);
        *(uint4*)(smf + OFF_PHI + row*FP_LD + lane*16) = hi4;
        *(uint4*)(smf + OFF_PLO + row*FP_LD + lane*16) = lo4;
    }
    __syncthreads();

    // ---- PV: warp w covers d in [w*8, w*8+8); write x bf16 hi/lo ----
    {
        float acc[2][4] = {};
        #pragma unroll 4
        for (int ks = 0; ks < 16; ks++) {
            int c0 = ks*32 + 4*tig;
            unsigned pa[2][4], pl[2][4], vb[2], vl[2];
            #pragma unroll
            for (int mi = 0; mi < 2; mi++) {
                int r0 = mi*16 + g;
                pa[mi][0] = *(const unsigned*)(smf + OFF_PHI + r0*FP_LD + c0);
                pa[mi][1] = *(const unsigned*)(smf + OFF_PHI + (r0+8)*FP_LD + c0);
                pa[mi][2] = *(const unsigned*)(smf + OFF_PHI + r0*FP_LD + c0 + 16);
                pa[mi][3] = *(const unsigned*)(smf + OFF_PHI + (r0+8)*FP_LD + c0 + 16);
                pl[mi][0] = *(const unsigned*)(smf + OFF_PLO + r0*FP_LD + c0);
                pl[mi][1] = *(const unsigned*)(smf + OFF_PLO + (r0+8)*FP_LD + c0);
                pl[mi][2] = *(const unsigned*)(smf + OFF_PLO + r0*FP_LD + c0 + 16);
                pl[mi][3] = *(const unsigned*)(smf + OFF_PLO + (r0+8)*FP_LD + c0 + 16);
            }
            int nr = w*8 + g;
            vb[0] = *(const unsigned*)(smf + OFF_VTHI + nr*FP_LD + c0);
            vb[1] = *(const unsigned*)(smf + OFF_VTHI + nr*FP_LD + c0 + 16);
            vl[0] = *(const unsigned*)(smf + OFF_VTLO + nr*FP_LD + c0);
            vl[1] = *(const unsigned*)(smf + OFF_VTLO + nr*FP_LD + c0 + 16);
            #pragma unroll
            for (int mi = 0; mi < 2; mi++) {
                mma_bf16(acc[mi], pa[mi], vb);
                mma_bf16(acc[mi], pl[mi], vb);
                mma_bf16(acc[mi], pa[mi], vl);
            }
        }
        #pragma unroll
        for (int mi = 0; mi < 2; mi++) {
            int row = i0 + mi*16 + g;
            int col = h*64 + w*8 + 2*tig;
            int idx0 = (b*NN + row)*HIDD + col;
            int idx1 = (b*NN + row + 8)*HIDD + col;
            *(unsigned*)&g_Ahi[idx0] = pk(acc[mi][0], acc[mi][1]);
            *(unsigned*)&g_Alo[idx0] = pklo(acc[mi][0], acc[mi][1]);
            *(unsigned*)&g_Ahi[idx1] = pk(acc[mi][2], acc[mi][3]);
            *(unsigned*)&g_Alo[idx1] = pklo(acc[mi][2], acc[mi][3]);
        }
    }
}

// ===========================================================================
extern "C" void kernel_launch(void* const* d_in, const int* in_sizes, int n_in,
                              void* d_out, int out_size)
{
    const float* q     = (const float*)d_in[0];
    const float* k     = (const float*)d_in[1];
    const float* v     = (const float*)d_in[2];
    const float* tbias = (const float*)d_in[3];
    const float* fs    = (const float*)d_in[4];
    const float* fo    = (const float*)d_in[5];
    const float* Wq    = (const float*)d_in[6];
    const float* bq    = (const float*)d_in[7];
    const float* Wk    = (const float*)d_in[8];
    const float* bk    = (const float*)d_in[9];
    const float* Wv    = (const float*)d_in[10];
    const float* bv    = (const float*)d_in[11];
    const float* Wo    = (const float*)d_in[12];
    const float* bo    = (const float*)d_in[13];
    const float* fsW1  = (const float*)d_in[14];
    const float* fsb1  = (const float*)d_in[15];
    const float* fsW2  = (const float*)d_in[16];
    const float* fsb2  = (const float*)d_in[17];
    const float* foW1  = (const float*)d_in[18];
    const float* fob1  = (const float*)d_in[19];
    const float* foW2  = (const float*)d_in[20];
    const float* fob2  = (const float*)d_in[21];
    float* out = (float*)d_out;

    float* vh; cudaGetSymbolAddress((void**)&vh, g_vh);
    __nv_bfloat16* Ahi;  cudaGetSymbolAddress((void**)&Ahi,  g_Ahi);
    __nv_bfloat16* Alo;  cudaGetSymbolAddress((void**)&Alo,  g_Alo);
    __nv_bfloat16* WhiT; cudaGetSymbolAddress((void**)&WhiT, g_WhiT);
    __nv_bfloat16* WloT; cudaGetSymbolAddress((void**)&WloT, g_WloT);
    __nv_bfloat16* qhh;  cudaGetSymbolAddress((void**)&qhh,  g_qhh);
    __nv_bfloat16* qhl;  cudaGetSymbolAddress((void**)&qhl,  g_qhl);
    __nv_bfloat16* khh;  cudaGetSymbolAddress((void**)&khh,  g_khh);
    __nv_bfloat16* khl;  cudaGetSymbolAddress((void**)&khl,  g_khl);

    cudaFuncSetAttribute(gemm_hmma_kernel,
                         cudaFuncAttributeMaxDynamicSharedMemorySize, SMEM_HM);
    cudaFuncSetAttribute(pair_mma_kernel,
                         cudaFuncAttributeMaxDynamicSharedMemorySize, PAIR_SMEMF*4);
    cudaFuncSetAttribute(attn_fused_kernel,
                         cudaFuncAttributeMaxDynamicSharedMemorySize, SMEM_FUSED);

    const int n4 = BN*HIDD/4;
    dim3 gw(16, 16);
    dim3 ghm(4, 32);

    // Q projection -> bf16 hi/lo (scale folds 1/sqrt(dk))
    prep_a_kernel<<<(n4 + 255)/256, 256>>>(q, Ahi, Alo, n4);
    prep_w_kernel<<<gw, 256>>>(Wq, WhiT, WloT);
    gemm_hmma_kernel<<<ghm, 256, SMEM_HM>>>(Ahi, Alo, WhiT, WloT, bq,
                                            nullptr, qhh, qhl, 0.125f);
    // K projection -> bf16 hi/lo
    prep_a_kernel<<<(n4 + 255)/256, 256>>>(k, Ahi, Alo, n4);
    prep_w_kernel<<<gw, 256>>>(Wk, WhiT, WloT);
    gemm_hmma_kernel<<<ghm, 256, SMEM_HM>>>(Ahi, Alo, WhiT, WloT, bk,
                                            nullptr, khh, khl, 1.0f);
    // V projection -> fp32
    prep_a_kernel<<<(n4 + 255)/256, 256>>>(v, Ahi, Alo, n4);
    prep_w_kernel<<<gw, 256>>>(Wv, WhiT, WloT);
    gemm_hmma_kernel<<<ghm, 256, SMEM_HM>>>(Ahi, Alo, WhiT, WloT, bv,
                                            vh, nullptr, nullptr, 1.0f);

    hfeat_kernel<<<(BN*MLPH + 255)/256, 256>>>(fs, fo, fsW1, fsb1, foW1, fob1);

    // pair bias -> g_scores (store mode, 0.1 folded)
    pair_mma_kernel<<<dim3(16, BB), 256, PAIR_SMEMF*4>>>(fs, fo, fsW1, fsW2, fsb2,
                                                         foW1, foW2, fob2);

    // fused QK + biases + softmax + PV -> x bf16 hi/lo in g_Ahi/g_Alo
    attn_fused_kernel<<<dim3(8, BB*HH), 256, SMEM_FUSED>>>(tbias);

    // Output projection (consumes g_Ahi/g_Alo directly)
    prep_w_kernel<<<gw, 256>>>(Wo, WhiT, WloT);
    gemm_hmma_kernel<<<ghm, 256, SMEM_HM>>>(Ahi, Alo, WhiT, WloT, bo,
                                            out, nullptr, nullptr, 1.0f);
}

// round 17
// speedup vs baseline: 1.5314x; 1.5314x over previous
#include <cuda_runtime.h>
#include <cuda_bf16.h>

#define BB 16
#define NN 256
#define HIDD 512
#define HH 8
#define MLPH 64
#define BN (BB*NN)   // 4096

__device__ __align__(256) float g_vh[BN*HIDD];
__device__ __align__(256) float g_x [BN*HIDD];
__device__ __align__(256) float g_scores[BB*HH*NN*NN];
__device__ __align__(256) float g_hiS[BN*MLPH];
__device__ __align__(256) float g_hiO[BN*MLPH];
__device__ __align__(256) __nv_bfloat16 g_Ahi[BN*HIDD];
__device__ __align__(256) __nv_bfloat16 g_Alo[BN*HIDD];
__device__ __align__(256) __nv_bfloat16 g_WhiT[HIDD*HIDD];
__device__ __align__(256) __nv_bfloat16 g_WloT[HIDD*HIDD];
__device__ __align__(256) __nv_bfloat16 g_qhh[BN*HIDD];
__device__ __align__(256) __nv_bfloat16 g_qhl[BN*HIDD];
__device__ __align__(256) __nv_bfloat16 g_khh[BN*HIDD];
__device__ __align__(256) __nv_bfloat16 g_khl[BN*HIDD];

// ============================ small asm helpers =============================
__device__ __forceinline__ unsigned smem_u32(const void* p) {
    unsigned a;
    asm("{ .reg .u64 t; cvta.to.shared.u64 t, %1; cvt.u32.u64 %0, t; }"
        : "=r"(a) : "l"(p));
    return a;
}
__device__ __forceinline__ void cp16(unsigned dst, const void* src) {
    asm volatile("cp.async.cg.shared.global [%0], [%1], 16;"
                 :: "r"(dst), "l"(src) : "memory");
}
__device__ __forceinline__ void cp_commit() {
    asm volatile("cp.async.commit_group;" ::: "memory");
}
__device__ __forceinline__ void mma_bf16(float* d, const unsigned* a, const unsigned* b) {
    asm volatile("mma.sync.aligned.m16n8k16.row.col.f32.bf16.bf16.f32 "
                 "{%0,%1,%2,%3}, {%4,%5,%6,%7}, {%8,%9}, {%0,%1,%2,%3};"
                 : "+f"(d[0]), "+f"(d[1]), "+f"(d[2]), "+f"(d[3])
                 : "r"(a[0]), "r"(a[1]), "r"(a[2]), "r"(a[3]),
                   "r"(b[0]), "r"(b[1]));
}
__device__ __forceinline__ unsigned pk(float a, float b) {
    __nv_bfloat162 v = __floats2bfloat162_rn(a, b);
    return *(unsigned*)&v;
}
__device__ __forceinline__ float resid(float x) {
    return x - __bfloat162float(__float2bfloat16_rn(x));
}
__device__ __forceinline__ unsigned pklo(float a, float b) {
    return pk(resid(a), resid(b));
}

// =================== prep: fp32 -> bf16 hi/lo ===============================
__global__ void prep_a_kernel(const float* __restrict__ A,
                              __nv_bfloat16* __restrict__ hi,
                              __nv_bfloat16* __restrict__ lo, int n4)
{
    int i = blockIdx.x * blockDim.x + threadIdx.x;
    if (i >= n4) return;
    float4 a = ((const float4*)A)[i];
    __nv_bfloat16 h0 = __float2bfloat16(a.x), h1 = __float2bfloat16(a.y);
    __nv_bfloat16 h2 = __float2bfloat16(a.z), h3 = __float2bfloat16(a.w);
    __nv_bfloat16 l0 = __float2bfloat16(a.x - __bfloat162float(h0));
    __nv_bfloat16 l1 = __float2bfloat16(a.y - __bfloat162float(h1));
    __nv_bfloat16 l2 = __float2bfloat16(a.z - __bfloat162float(h2));
    __nv_bfloat16 l3 = __float2bfloat16(a.w - __bfloat162float(h3));
    ((__nv_bfloat162*)hi)[i*2]   = __nv_bfloat162(h0, h1);
    ((__nv_bfloat162*)hi)[i*2+1] = __nv_bfloat162(h2, h3);
    ((__nv_bfloat162*)lo)[i*2]   = __nv_bfloat162(l0, l1);
    ((__nv_bfloat162*)lo)[i*2+1] = __nv_bfloat162(l2, l3);
}

// W[k][n] -> WT[n][k] bf16 hi/lo (tiled transpose)
__global__ __launch_bounds__(256) void prep_w_kernel(
    const float* __restrict__ W,
    __nv_bfloat16* __restrict__ hiT, __nv_bfloat16* __restrict__ loT)
{
    __shared__ float tile[32][33];
    int n0 = blockIdx.x*32, k0 = blockIdx.y*32;
    int tx = threadIdx.x & 31, ty = threadIdx.x >> 5;
    for (int r = ty; r < 32; r += 8)
        tile[r][tx] = W[(k0 + r)*512 + n0 + tx];
    __syncthreads();
    for (int rn = ty; rn < 32; rn += 8) {
        float w = tile[tx][rn];
        __nv_bfloat16 h = __float2bfloat16(w);
        __nv_bfloat16 l = __float2bfloat16(w - __bfloat162float(h));
        hiT[(n0 + rn)*512 + k0 + tx] = h;
        loT[(n0 + rn)*512 + k0 + tx] = l;
    }
}

// =================== HMMA GEMM: out = scale*(A@W + bias) ====================
// If C != nullptr: write fp32 C. Else: write bf16 hi/lo to Chi/Clo.
#define LDAB 80
#define ARR_B (128*LDAB)
#define STAGE_B (4*ARR_B)
#define SMEM_HM (2*STAGE_B)

__global__ __launch_bounds__(256, 1) void gemm_hmma_kernel(
    const __nv_bfloat16* __restrict__ Ahi, const __nv_bfloat16* __restrict__ Alo,
    const __nv_bfloat16* __restrict__ Bhi, const __nv_bfloat16* __restrict__ Blo,
    const float* __restrict__ bias, float* __restrict__ C,
    __nv_bfloat16* __restrict__ Chi, __nv_bfloat16* __restrict__ Clo, float scale)
{
    extern __shared__ char smc[];
    unsigned sb = smem_u32(smc);
    int t = threadIdx.x, lane = t & 31, wid = t >> 5;
    int m0 = blockIdx.y*128, n0 = blockIdx.x*128;
    int wm = (wid >> 2)*64, wn = (wid & 3)*32;
    int g = lane >> 2, tig = lane & 3;

    float acc[4][4][4] = {};

    auto stage_load = [&](int kc, int s) {
        unsigned base = sb + s*STAGE_B;
        #pragma unroll
        for (int i = 0; i < 2; i++) {
            int idx = t + i*256;
            int r = idx >> 2;
            int cb = (idx & 3)*16;
            unsigned d = base + r*LDAB + cb;
            int goff = kc + cb/2;
            cp16(d,            &Ahi[(m0 + r)*512 + goff]);
            cp16(d + ARR_B,    &Alo[(m0 + r)*512 + goff]);
            cp16(d + 2*ARR_B,  &Bhi[(n0 + r)*512 + goff]);
            cp16(d + 3*ARR_B,  &Blo[(n0 + r)*512 + goff]);
        }
        cp_commit();
    };

    stage_load(0, 0);
    stage_load(32, 1);

    #pragma unroll 1
    for (int kc = 0; kc < 16; kc++) {
        int s = kc & 1;
        if (kc == 15) asm volatile("cp.async.wait_group 0;" ::: "memory");
        else          asm volatile("cp.async.wait_group 1;" ::: "memory");
        __syncthreads();

        const char* stg = smc + s*STAGE_B;

        #pragma unroll
        for (int ks = 0; ks < 32; ks += 16) {
            unsigned ah[4][4], al[4][4], bh[4][2], bl[4][2];
            #pragma unroll
            for (int mi = 0; mi < 4; mi++) {
                int r0 = wm + mi*16 + g;
                int c0 = (ks + 2*tig)*2;
                ah[mi][0] = *(const unsigned*)(stg + r0*LDAB + c0);
                ah[mi][1] = *(const unsigned*)(stg + (r0+8)*LDAB + c0);
                ah[mi][2] = *(const unsigned*)(stg + r0*LDAB + c0 + 16);
                ah[mi][3] = *(const unsigned*)(stg + (r0+8)*LDAB + c0 + 16);
                al[mi][0] = *(const unsigned*)(stg + ARR_B + r0*LDAB + c0);
                al[mi][1] = *(const unsigned*)(stg + ARR_B + (r0+8)*LDAB + c0);
                al[mi][2] = *(const unsigned*)(stg + ARR_B + r0*LDAB + c0 + 16);
                al[mi][3] = *(const unsigned*)(stg + ARR_B + (r0+8)*LDAB + c0 + 16);
            }
            #pragma unroll
            for (int ni = 0; ni < 4; ni++) {
                int nr = wn + ni*8 + g;
                int c0 = (ks + 2*tig)*2;
                bh[ni][0] = *(const unsigned*)(stg + 2*ARR_B + nr*LDAB + c0);
                bh[ni][1] = *(const unsigned*)(stg + 2*ARR_B + nr*LDAB + c0 + 16);
                bl[ni][0] = *(const unsigned*)(stg + 3*ARR_B + nr*LDAB + c0);
                bl[ni][1] = *(const unsigned*)(stg + 3*ARR_B + nr*LDAB + c0 + 16);
            }
            #pragma unroll
            for (int mi = 0; mi < 4; mi++)
                #pragma unroll
                for (int ni = 0; ni < 4; ni++) {
                    mma_bf16(acc[mi][ni], ah[mi], bh[ni]);
                    mma_bf16(acc[mi][ni], ah[mi], bl[ni]);
                    mma_bf16(acc[mi][ni], al[mi], bh[ni]);
                }
        }
        __syncthreads();
        if (kc + 2 < 16) stage_load((kc + 2)*32, s);
    }

    #pragma unroll
    for (int mi = 0; mi < 4; mi++) {
        int row = m0 + wm + mi*16 + g;
        #pragma unroll
        for (int ni = 0; ni < 4; ni++) {
            int col = n0 + wn + ni*8 + 2*tig;
            float b0 = bias[col], b1 = bias[col + 1];
            float o00 = scale*(acc[mi][ni][0] + b0);
            float o01 = scale*(acc[mi][ni][1] + b1);
            float o10 = scale*(acc[mi][ni][2] + b0);
            float o11 = scale*(acc[mi][ni][3] + b1);
            if (C) {
                *(float2*)&C[row*512 + col]       = make_float2(o00, o01);
                *(float2*)&C[(row + 8)*512 + col] = make_float2(o10, o11);
            } else {
                *(unsigned*)&Chi[row*512 + col]       = pk(o00, o01);
                *(unsigned*)&Clo[row*512 + col]       = pklo(o00, o01);
                *(unsigned*)&Chi[(row + 8)*512 + col] = pk(o10, o11);
                *(unsigned*)&Clo[(row + 8)*512 + col] = pklo(o10, o11);
            }
        }
    }
}

// ============================ hfeat: hi = feat@Wa + b1 ======================
__global__ void hfeat_kernel(
    const float* __restrict__ fs, const float* __restrict__ fo,
    const float* __restrict__ fsW1, const float* __restrict__ fsb1,
    const float* __restrict__ foW1, const float* __restrict__ fob1)
{
    int idx = blockIdx.x * blockDim.x + threadIdx.x;
    if (idx >= BN*MLPH) return;
    int bn = idx >> 6, m = idx & 63;
    float s_i = fsb1[m], o_i = fob1[m];
    #pragma unroll
    for (int f = 0; f < 8; f++) {
        float vs = fs[bn*8 + f], vo = fo[bn*8 + f];
        s_i += vs * fsW1[f*64 + m];
        o_i += vo * foW1[f*64 + m];
    }
    g_hiS[idx] = s_i; g_hiO[idx] = o_i;
}

// =================== scores via HMMA: S = Q.K^T + tbias =====================
// CTA = 128i x 128j per (b,h). Q/K bf16 hi/lo staged via cp.async, K=64.
#define SC_LD 144                  // 64 bf16 = 128B + 16 pad
#define SC_ARR (128*SC_LD)         // 18432
#define SMEM_SC (4*SC_ARR)         // 73728

__global__ __launch_bounds__(256) void scores_mma_kernel(const float* __restrict__ tbias)
{
    extern __shared__ char sms[];
    unsigned sb = smem_u32(sms);
    int t = threadIdx.x, lane = t & 31, wid = t >> 5;
    int g = lane >> 2, tig = lane & 3;
    int j0 = blockIdx.x*128, i0 = blockIdx.y*128;
    int bh = blockIdx.z; int b = bh >> 3, h = bh & 7;
    int wm = (wid >> 2)*64, wn = (wid & 3)*32;

    // stage Q (128x64) and K (128x64) hi/lo
    #pragma unroll
    for (int it = 0; it < 4; it++) {
        int idx = t + it*256;
        int r = idx >> 3, cb = (idx & 7)*16;
        int gq = (b*NN + i0 + r)*HIDD + h*64;
        int gk = (b*NN + j0 + r)*HIDD + h*64;
        cp16(sb + r*SC_LD + cb,            (const char*)&g_qhh[gq] + cb);
        cp16(sb + SC_ARR + r*SC_LD + cb,   (const char*)&g_qhl[gq] + cb);
        cp16(sb + 2*SC_ARR + r*SC_LD + cb, (const char*)&g_khh[gk] + cb);
        cp16(sb + 3*SC_ARR + r*SC_LD + cb, (const char*)&g_khl[gk] + cb);
    }
    cp_commit();
    asm volatile("cp.async.wait_group 0;" ::: "memory");
    __syncthreads();

    float acc[4][4][4] = {};
    #pragma unroll
    for (int ks = 0; ks < 64; ks += 16) {
        unsigned ah[4][4], al[4][4], bhf[4][2], blf[4][2];
        int c0 = (ks + 2*tig)*2;
        #pragma unroll
        for (int mi = 0; mi < 4; mi++) {
            int r0 = wm + mi*16 + g;
            ah[mi][0] = *(const unsigned*)(sms + r0*SC_LD + c0);
            ah[mi][1] = *(const unsigned*)(sms + (r0+8)*SC_LD + c0);
            ah[mi][2] = *(const unsigned*)(sms + r0*SC_LD + c0 + 16);
            ah[mi][3] = *(const unsigned*)(sms + (r0+8)*SC_LD + c0 + 16);
            al[mi][0] = *(const unsigned*)(sms + SC_ARR + r0*SC_LD + c0);
            al[mi][1] = *(const unsigned*)(sms + SC_ARR + (r0+8)*SC_LD + c0);
            al[mi][2] = *(const unsigned*)(sms + SC_ARR + r0*SC_LD + c0 + 16);
            al[mi][3] = *(const unsigned*)(sms + SC_ARR + (r0+8)*SC_LD + c0 + 16);
        }
        #pragma unroll
        for (int ni = 0; ni < 4; ni++) {
            int nr = wn + ni*8 + g;
            bhf[ni][0] = *(const unsigned*)(sms + 2*SC_ARR + nr*SC_LD + c0);
            bhf[ni][1] = *(const unsigned*)(sms + 2*SC_ARR + nr*SC_LD + c0 + 16);
            blf[ni][0] = *(const unsigned*)(sms + 3*SC_ARR + nr*SC_LD + c0);
            blf[ni][1] = *(const unsigned*)(sms + 3*SC_ARR + nr*SC_LD + c0 + 16);
        }
        #pragma unroll
        for (int mi = 0; mi < 4; mi++)
            #pragma unroll
            for (int ni = 0; ni < 4; ni++) {
                mma_bf16(acc[mi][ni], ah[mi], bhf[ni]);
                mma_bf16(acc[mi][ni], ah[mi], blf[ni]);
                mma_bf16(acc[mi][ni], al[mi], bhf[ni]);
            }
    }

    #pragma unroll
    for (int mi = 0; mi < 4; mi++) {
        int row = i0 + wm + mi*16 + g;
        #pragma unroll
        for (int ni = 0; ni < 4; ni++) {
            int col = j0 + wn + ni*8 + 2*tig;
            long base0 = ((long)(b*HH + h)*NN + row)*NN + col;
            long base1 = base0 + (long)8*NN;
            float2 t0 = *(const float2*)&tbias[base0];
            float2 t1 = *(const float2*)&tbias[base1];
            *(float2*)&g_scores[base0] = make_float2(acc[mi][ni][0] + t0.x,
                                                     acc[mi][ni][1] + t0.y);
            *(float2*)&g_scores[base1] = make_float2(acc[mi][ni][2] + t1.x,
                                                     acc[mi][ni][3] + t1.y);
        }
    }
}

// =================== pair bias via back-to-back HMMA (RMW mode) =============
#define PAIR_SMEMF 12288
#define FB1(ml,nt,r,hl) fb1[((((ml)*8+(nt))*2+(r))*2+(hl))*32 + lane]
#define FB2(ml,ks,r,hl) fb2[((((ml)*4+(ks))*2+(r))*2+(hl))*32 + lane]

__global__ __launch_bounds__(256) void pair_mma_kernel(
    const float* __restrict__ fs, const float* __restrict__ fo,
    const float* __restrict__ fsW1, const float* __restrict__ fsW2, const float* __restrict__ fsb2,
    const float* __restrict__ foW1, const float* __restrict__ foW2, const float* __restrict__ fob2)
{
    extern __shared__ float ps[];
    float* sW1 = ps;
    float* sW2 = ps + 2048;
    float* sF  = ps + 3072;
    float* sHi = ps + 7168;
    unsigned* fb1 = (unsigned*)(ps + 9216);
    unsigned* fb2 = (unsigned*)(ps + 11264);

    int t = threadIdx.x, lane = t & 31, w = t >> 5;
    int g = lane >> 2;
    int tig = lane & 3;
    int ig = blockIdx.x, b = blockIdx.y;
    int i0 = ig*16;

    for (int idx = t; idx < 1024; idx += 256) {
        int r = idx >> 6, c = idx & 63;
        sW1[idx]        = fsW1[(8+r)*64 + c];
        sW1[1024+idx]   = foW1[(8+r)*64 + c];
        sHi[idx]        = g_hiS[(b*NN + i0 + r)*64 + c];
        sHi[1024+idx]   = g_hiO[(b*NN + i0 + r)*64 + c];
    }
    for (int idx = t; idx < 512; idx += 256) {
        sW2[idx]       = fsW2[idx];
        sW2[512+idx]   = foW2[idx];
    }
    for (int idx = t; idx < 2048; idx += 256) {
        sF[idx]        = fs[b*NN*8 + idx];
        sF[2048+idx]   = fo[b*NN*8 + idx];
    }
    __syncthreads();

    if (w == 0) {
        #pragma unroll
        for (int ml = 0; ml < 2; ml++)
            #pragma unroll
            for (int nt = 0; nt < 8; nt++) {
                int n = nt*8 + g;
                const float* W = sW1 + ml*1024;
                float w00 = W[(2*tig+8)*64 + n], w01 = W[(2*tig+9)*64 + n];
                float w10 = W[(2*tig)*64 + n],   w11 = W[(2*tig+1)*64 + n];
                FB1(ml,nt,0,0) = pk(w00, w01);
                FB1(ml,nt,0,1) = pklo(w00, w01);
                FB1(ml,nt,1,0) = pk(w10, w11);
                FB1(ml,nt,1,1) = pklo(w10, w11);
            }
    } else if (w == 1) {
        #pragma unroll
        for (int ml = 0; ml < 2; ml++)
            #pragma unroll
            for (int ks = 0; ks < 4; ks++) {
                const float* W = sW2 + ml*512;
                float w00 = W[(16*ks+2*tig)*8 + g],   w01 = W[(16*ks+2*tig+1)*8 + g];
                float w10 = W[(16*ks+2*tig+8)*8 + g], w11 = W[(16*ks+2*tig+9)*8 + g];
                FB2(ml,ks,0,0) = pk(w00, w01);
                FB2(ml,ks,0,1) = pklo(w00, w01);
                FB2(ml,ks,1,0) = pk(w10, w11);
                FB2(ml,ks,1,1) = pklo(w10, w11);
            }
    }
    __syncthreads();

    float b2r[2][2];
    b2r[0][0] = fsb2[2*tig]; b2r[0][1] = fsb2[2*tig+1];
    b2r[1][0] = fob2[2*tig]; b2r[1][1] = fob2[2*tig+1];

    float accL1[8][4];
    unsigned upk[8][2];

    #pragma unroll 1
    for (int jh = 0; jh < 2; jh++) {
        int jbase = jh*128 + w*16;
        float fjv[2][2][2];
        unsigned fa2h[2], fa3h[2], fa2l[2], fa3l[2];
        #pragma unroll
        for (int ml = 0; ml < 2; ml++) {
            const float* F = sF + ml*2048;
            float f00 = F[(jbase+g)*8 + 2*tig],   f01 = F[(jbase+g)*8 + 2*tig+1];
            float f10 = F[(jbase+g+8)*8 + 2*tig], f11 = F[(jbase+g+8)*8 + 2*tig+1];
            fjv[ml][0][0] = f00; fjv[ml][0][1] = f01;
            fjv[ml][1][0] = f10; fjv[ml][1][1] = f11;
            fa2h[ml] = pk(f00, f01); fa2l[ml] = pklo(f00, f01);
            fa3h[ml] = pk(f10, f11); fa3l[ml] = pklo(f10, f11);
        }

        #pragma unroll 1
        for (int ii = 0; ii < 16; ii++) {
            float pacc[4] = {0.f, 0.f, 0.f, 0.f};
            #pragma unroll
            for (int ml = 0; ml < 2; ml++) {
                const float* F = sF + ml*2048;
                float fi0 = F[(i0+ii)*8 + 2*tig], fi1 = F[(i0+ii)*8 + 2*tig+1];
                float d00 = fabsf(fi0 - fjv[ml][0][0]), d01 = fabsf(fi1 - fjv[ml][0][1]);
                float d10 = fabsf(fi0 - fjv[ml][1][0]), d11 = fabsf(fi1 - fjv[ml][1][1]);
                unsigned ah[4], al[4];
                ah[0] = pk(d00, d01);  ah[1] = pk(d10, d11);
                ah[2] = fa2h[ml];      ah[3] = fa3h[ml];
                al[0] = pklo(d00, d01); al[1] = pklo(d10, d11);
                al[2] = fa2l[ml];      al[3] = fa3l[ml];

                const float* Hi = sHi + ml*1024 + ii*64;
                #pragma unroll
                for (int nt = 0; nt < 8; nt++) {
                    float h0 = Hi[8*nt + 2*tig], h1 = Hi[8*nt + 2*tig + 1];
                    accL1[nt][0] = h0; accL1[nt][1] = h1;
                    accL1[nt][2] = h0; accL1[nt][3] = h1;
                    unsigned bh[2] = {FB1(ml,nt,0,0), FB1(ml,nt,1,0)};
                    unsigned bl[2] = {FB1(ml,nt,0,1), FB1(ml,nt,1,1)};
                    mma_bf16(accL1[nt], ah, bh);
                    mma_bf16(accL1[nt], al, bh);
                    mma_bf16(accL1[nt], ah, bl);
                }
                #pragma unroll
                for (int nt = 0; nt < 8; nt++) {
                    upk[nt][0] = pk(fmaxf(accL1[nt][0], 0.f), fmaxf(accL1[nt][1], 0.f));
                    upk[nt][1] = pk(fmaxf(accL1[nt][2], 0.f), fmaxf(accL1[nt][3], 0.f));
                }
                float acc2[4];
                acc2[0] = b2r[ml][0]; acc2[1] = b2r[ml][1];
                acc2[2] = b2r[ml][0]; acc2[3] = b2r[ml][1];
                #pragma unroll
                for (int ks = 0; ks < 4; ks++) {
                    unsigned a2[4] = {upk[2*ks][0], upk[2*ks][1],
                                      upk[2*ks+1][0], upk[2*ks+1][1]};
                    unsigned bh2[2] = {FB2(ml,ks,0,0), FB2(ml,ks,1,0)};
                    unsigned bl2[2] = {FB2(ml,ks,0,1), FB2(ml,ks,1,1)};
                    mma_bf16(acc2, a2, bh2);
                    mma_bf16(acc2, a2, bl2);
                }
                pacc[0] += acc2[0]; pacc[1] += acc2[1];
                pacc[2] += acc2[2]; pacc[3] += acc2[3];
            }
            int i = i0 + ii;
            float* s0 = &g_scores[((b*HH + 2*tig)*NN + i)*NN + jbase];
            float* s1 = &g_scores[((b*HH + 2*tig + 1)*NN + i)*NN + jbase];
            s0[g]     += 0.1f * pacc[0];
            s1[g]     += 0.1f * pacc[1];
            s0[g + 8] += 0.1f * pacc[2];
            s1[g + 8] += 0.1f * pacc[3];
        }
    }
}

// ============================ softmax ======================================
__global__ void softmax_kernel()
{
    int warp = (blockIdx.x * blockDim.x + threadIdx.x) >> 5;
    int lane = threadIdx.x & 31;
    if (warp >= BB*HH*NN) return;
    float* row = &g_scores[(size_t)warp * NN];
    float4 v0 = *(float4*)&row[lane*8];
    float4 v1 = *(float4*)&row[lane*8 + 4];
    float mx = fmaxf(fmaxf(fmaxf(v0.x, v0.y), fmaxf(v0.z, v0.w)),
                     fmaxf(fmaxf(v1.x, v1.y), fmaxf(v1.z, v1.w)));
    #pragma unroll
    for (int o = 16; o > 0; o >>= 1)
        mx = fmaxf(mx, __shfl_xor_sync(0xffffffffu, mx, o));
    v0.x = __expf(v0.x - mx); v0.y = __expf(v0.y - mx);
    v0.z = __expf(v0.z - mx); v0.w = __expf(v0.w - mx);
    v1.x = __expf(v1.x - mx); v1.y = __expf(v1.y - mx);
    v1.z = __expf(v1.z - mx); v1.w = __expf(v1.w - mx);
    float sm = v0.x + v0.y + v0.z + v0.w + v1.x + v1.y + v1.z + v1.w;
    #pragma unroll
    for (int o = 16; o > 0; o >>= 1)
        sm += __shfl_xor_sync(0xffffffffu, sm, o);
    float inv = 1.f / sm;
    v0.x *= inv; v0.y *= inv; v0.z *= inv; v0.w *= inv;
    v1.x *= inv; v1.y *= inv; v1.z *= inv; v1.w *= inv;
    *(float4*)&row[lane*8]     = v0;
    *(float4*)&row[lane*8 + 4] = v1;
}

// ============================ attnv (SIMT, proven) ==========================
__global__ __launch_bounds__(256) void attnv_kernel()
{
    __shared__ float As[64*68];
    __shared__ float Vs[64*68];
    int t  = threadIdx.x;
    int tx = t & 15, ty = t >> 4;
    int i0 = blockIdx.x * 64;
    int bh = blockIdx.y; int b = bh >> 3, h = bh & 7;
    float acc[4][4] = {};

    for (int jc = 0; jc < NN; jc += 64) {
        #pragma unroll
        for (int u = 0; u < 4; u++) {
            int idx = t + u*256;
            int r = idx >> 4, c4 = (idx & 15) * 4;
            float4 a4 = *(const float4*)&g_scores[((b*HH + h)*NN + i0 + r)*NN + jc + c4];
            As[(c4+0)*68 + r] = a4.x; As[(c4+1)*68 + r] = a4.y;
            As[(c4+2)*68 + r] = a4.z; As[(c4+3)*68 + r] = a4.w;
            float4 v4 = *(const float4*)&g_vh[(b*NN + jc + r)*HIDD + h*64 + c4];
            *(float4*)&Vs[r*68 + c4] = v4;
        }
        __syncthreads();
        #pragma unroll 8
        for (int j = 0; j < 64; j++) {
            float4 a4 = *(const float4*)&As[j*68 + ty*4];
            float4 b4 = *(const float4*)&Vs[j*68 + tx*4];
            float av[4] = {a4.x, a4.y, a4.z, a4.w};
            float bv[4] = {b4.x, b4.y, b4.z, b4.w};
            #pragma unroll
            for (int i = 0; i < 4; i++)
                #pragma unroll
                for (int j2 = 0; j2 < 4; j2++)
                    acc[i][j2] += av[i] * bv[j2];
        }
        __syncthreads();
    }
    #pragma unroll
    for (int i = 0; i < 4; i++) {
        float4 o = {acc[i][0], acc[i][1], acc[i][2], acc[i][3]};
        *(float4*)&g_x[(b*NN + i0 + ty*4 + i)*HIDD + h*64 + tx*4] = o;
    }
}

// ===========================================================================
extern "C" void kernel_launch(void* const* d_in, const int* in_sizes, int n_in,
                              void* d_out, int out_size)
{
    const float* q     = (const float*)d_in[0];
    const float* k     = (const float*)d_in[1];
    const float* v     = (const float*)d_in[2];
    const float* tbias = (const float*)d_in[3];
    const float* fs    = (const float*)d_in[4];
    const float* fo    = (const float*)d_in[5];
    const float* Wq    = (const float*)d_in[6];
    const float* bq    = (const float*)d_in[7];
    const float* Wk    = (const float*)d_in[8];
    const float* bk    = (const float*)d_in[9];
    const float* Wv    = (const float*)d_in[10];
    const float* bv    = (const float*)d_in[11];
    const float* Wo    = (const float*)d_in[12];
    const float* bo    = (const float*)d_in[13];
    const float* fsW1  = (const float*)d_in[14];
    const float* fsb1  = (const float*)d_in[15];
    const float* fsW2  = (const float*)d_in[16];
    const float* fsb2  = (const float*)d_in[17];
    const float* foW1  = (const float*)d_in[18];
    const float* fob1  = (const float*)d_in[19];
    const float* foW2  = (const float*)d_in[20];
    const float* fob2  = (const float*)d_in[21];
    float* out = (float*)d_out;

    float* vh; cudaGetSymbolAddress((void**)&vh, g_vh);
    float* x;  cudaGetSymbolAddress((void**)&x,  g_x);
    __nv_bfloat16* Ahi;  cudaGetSymbolAddress((void**)&Ahi,  g_Ahi);
    __nv_bfloat16* Alo;  cudaGetSymbolAddress((void**)&Alo,  g_Alo);
    __nv_bfloat16* WhiT; cudaGetSymbolAddress((void**)&WhiT, g_WhiT);
    __nv_bfloat16* WloT; cudaGetSymbolAddress((void**)&WloT, g_WloT);
    __nv_bfloat16* qhh;  cudaGetSymbolAddress((void**)&qhh,  g_qhh);
    __nv_bfloat16* qhl;  cudaGetSymbolAddress((void**)&qhl,  g_qhl);
    __nv_bfloat16* khh;  cudaGetSymbolAddress((void**)&khh,  g_khh);
    __nv_bfloat16* khl;  cudaGetSymbolAddress((void**)&khl,  g_khl);

    cudaFuncSetAttribute(gemm_hmma_kernel,
                         cudaFuncAttributeMaxDynamicSharedMemorySize, SMEM_HM);
    cudaFuncSetAttribute(pair_mma_kernel,
                         cudaFuncAttributeMaxDynamicSharedMemorySize, PAIR_SMEMF*4);
    cudaFuncSetAttribute(scores_mma_kernel,
                         cudaFuncAttributeMaxDynamicSharedMemorySize, SMEM_SC);

    const int n4 = BN*HIDD/4;
    dim3 gw(16, 16);
    dim3 ghm(4, 32);

    // Q projection -> bf16 hi/lo (scale folds 1/sqrt(dk))
    prep_a_kernel<<<(n4 + 255)/256, 256>>>(q, Ahi, Alo, n4);
    prep_w_kernel<<<gw, 256>>>(Wq, WhiT, WloT);
    gemm_hmma_kernel<<<ghm, 256, SMEM_HM>>>(Ahi, Alo, WhiT, WloT, bq,
                                            nullptr, qhh, qhl, 0.125f);
    // K projection -> bf16 hi/lo
    prep_a_kernel<<<(n4 + 255)/256, 256>>>(k, Ahi, Alo, n4);
    prep_w_kernel<<<gw, 256>>>(Wk, WhiT, WloT);
    gemm_hmma_kernel<<<ghm, 256, SMEM_HM>>>(Ahi, Alo, WhiT, WloT, bk,
                                            nullptr, khh, khl, 1.0f);
    // V projection -> fp32
    prep_a_kernel<<<(n4 + 255)/256, 256>>>(v, Ahi, Alo, n4);
    prep_w_kernel<<<gw, 256>>>(Wv, WhiT, WloT);
    gemm_hmma_kernel<<<ghm, 256, SMEM_HM>>>(Ahi, Alo, WhiT, WloT, bv,
                                            vh, nullptr, nullptr, 1.0f);

    hfeat_kernel<<<(BN*MLPH + 255)/256, 256>>>(fs, fo, fsW1, fsb1, foW1, fob1);

    // scores = Q.K^T + tbias  (HMMA)
    scores_mma_kernel<<<dim3(2, 2, BB*HH), 256, SMEM_SC>>>(tbias);

    // pair bias RMW into scores
    pair_mma_kernel<<<dim3(16, BB), 256, PAIR_SMEMF*4>>>(fs, fo, fsW1, fsW2, fsb2,
                                                         foW1, foW2, fob2);

    softmax_kernel<<<(BB*HH*NN*32 + 255)/256, 256>>>();

    attnv_kernel<<<dim3(4, BB*HH), 256>>>();

    // Output projection (x -> hi/lo -> out)
    prep_a_kernel<<<(n4 + 255)/256, 256>>>(x, Ahi, Alo, n4);
    prep_w_kernel<<<gw, 256>>>(Wo, WhiT, WloT);
    gemm_hmma_kernel<<<ghm, 256, SMEM_HM>>>(Ahi, Alo, WhiT, WloT, bo,
                                            out, nullptr, nullptr, 1.0f);
}